// round 5
// baseline (speedup 1.0000x reference)
#include <cuda_runtime.h>
#include <cuda_bf16.h>
#include <cstdint>

// Problem dims (fixed):
// features [3200, 4096] f32, phrases [3200, 15, 1024] f32,
// W [1024, 4096] f32, b [1024] f32, phrase_lengths [3200] i32
// out [3200, 2048] f32 : cols 0..1023 = relu(A@W^T + b), cols 1024..2047 = phrase mean
#define M_DIM 3200
#define N_DIM 1024
#define K_DIM 4096
#define OUT_STRIDE 2048
#define L_DIM 15
#define D_DIM 1024

// ---------------- device-global split buffers ----------------
__device__ __nv_bfloat16 g_Ahi[(size_t)M_DIM * K_DIM];
__device__ __nv_bfloat16 g_Alo[(size_t)M_DIM * K_DIM];
__device__ __nv_bfloat16 g_Whi[(size_t)N_DIM * K_DIM];
__device__ __nv_bfloat16 g_Wlo[(size_t)N_DIM * K_DIM];

// ---------------- helpers ----------------
__device__ __forceinline__ uint32_t smem_to_u32(const void* p) {
    uint32_t a;
    asm("{ .reg .u64 t; cvta.to.shared.u64 t, %1; cvt.u32.u64 %0, t; }" : "=r"(a) : "l"(p));
    return a;
}
__device__ __forceinline__ void cp16(uint32_t dst, const void* src) {
    asm volatile("cp.async.cg.shared.global [%0], [%1], 16;" :: "r"(dst), "l"(src) : "memory");
}
#define CP_COMMIT() asm volatile("cp.async.commit_group;" ::: "memory")
#define CP_WAIT0()  asm volatile("cp.async.wait_group 0;" ::: "memory")

__device__ __forceinline__ void ldm_x4(uint32_t* r, uint32_t addr) {
    asm volatile("ldmatrix.sync.aligned.m8n8.x4.shared.b16 {%0,%1,%2,%3}, [%4];"
                 : "=r"(r[0]), "=r"(r[1]), "=r"(r[2]), "=r"(r[3]) : "r"(addr));
}
__device__ __forceinline__ void mma16816(float* c, const uint32_t* a, uint32_t b0, uint32_t b1) {
    asm volatile(
        "mma.sync.aligned.m16n8k16.row.col.f32.bf16.bf16.f32 "
        "{%0,%1,%2,%3}, {%4,%5,%6,%7}, {%8,%9}, {%0,%1,%2,%3};"
        : "+f"(c[0]), "+f"(c[1]), "+f"(c[2]), "+f"(c[3])
        : "r"(a[0]), "r"(a[1]), "r"(a[2]), "r"(a[3]), "r"(b0), "r"(b1));
}

// ---------------- fused split prepass: fp32 -> bf16 hi + lo (A and W) ----------------
__device__ __forceinline__ void split4(const float4 v, __nv_bfloat162* hi2, __nv_bfloat162* lo2, int i) {
    __nv_bfloat16 hx = __float2bfloat16(v.x);
    __nv_bfloat16 hy = __float2bfloat16(v.y);
    __nv_bfloat16 hz = __float2bfloat16(v.z);
    __nv_bfloat16 hw = __float2bfloat16(v.w);
    hi2[2 * i]     = __halves2bfloat162(hx, hy);
    hi2[2 * i + 1] = __halves2bfloat162(hz, hw);
    lo2[2 * i]     = __floats2bfloat162_rn(v.x - __bfloat162float(hx), v.y - __bfloat162float(hy));
    lo2[2 * i + 1] = __floats2bfloat162_rn(v.z - __bfloat162float(hz), v.w - __bfloat162float(hw));
}
#define A_N4 (M_DIM * K_DIM / 4)
#define W_N4 (N_DIM * K_DIM / 4)
__global__ __launch_bounds__(256)
void split_kernel(const float* __restrict__ A, const float* __restrict__ W) {
    __nv_bfloat162* Ahi2 = reinterpret_cast<__nv_bfloat162*>(g_Ahi);
    __nv_bfloat162* Alo2 = reinterpret_cast<__nv_bfloat162*>(g_Alo);
    __nv_bfloat162* Whi2 = reinterpret_cast<__nv_bfloat162*>(g_Whi);
    __nv_bfloat162* Wlo2 = reinterpret_cast<__nv_bfloat162*>(g_Wlo);
    const float4* a4 = reinterpret_cast<const float4*>(A);
    const float4* w4 = reinterpret_cast<const float4*>(W);
    for (int i = blockIdx.x * blockDim.x + threadIdx.x; i < A_N4 + W_N4;
         i += gridDim.x * blockDim.x) {
        if (i < A_N4) split4(a4[i], Ahi2, Alo2, i);
        else          split4(w4[i - A_N4], Whi2, Wlo2, i - A_N4);
    }
}

// ---------------- mma.sync GEMM: out[:, 0:1024] = relu(A@W^T + b) ----------------
// BM=128, BN=64, BK=32 bf16. 8 warps, warp grid 4x2, warp tile 32x32.
// 2-stage cp.async double buffer, 80B padded rows, 3 CTAs/SM.
#define BK 32
#define NC (K_DIM / BK)          // 128
#define ROW_B 80
#define A_TILE (128 * ROW_B)     // 10240
#define B_TILE (64 * ROW_B)      // 5120
#define STAGE_BYTES (2 * A_TILE + 2 * B_TILE)   // 30720
#define GEMM_SMEM (2 * STAGE_BYTES)             // 61440

__global__ __launch_bounds__(256, 3)
void gemm_mma_kernel(const float* __restrict__ bias, float* __restrict__ out) {
    extern __shared__ char smem[];
    const uint32_t sbase = smem_to_u32(smem);
    const int tid = threadIdx.x;
    const int wid = tid >> 5;
    const int lane = tid & 31;
    const int wm = wid >> 1;
    const int wn = wid & 1;
    const int bm = blockIdx.y * 128;
    const int bn = blockIdx.x * 64;

    const int a_row = tid >> 2;
    const int a_c   = tid & 3;

    auto load_chunk = [&](int chunk, int stage) {
        const int kt = chunk * BK;
        const uint32_t sb = sbase + (uint32_t)stage * STAGE_BYTES;
#pragma unroll
        for (int j = 0; j < 2; j++) {
            const int row = a_row + j * 64;
            const uint32_t off = (uint32_t)(row * ROW_B + a_c * 16);
            const size_t ga = (size_t)(bm + row) * K_DIM + kt + a_c * 8;
            cp16(sb + off,          g_Ahi + ga);
            cp16(sb + A_TILE + off, g_Alo + ga);
        }
        {
            const uint32_t off = (uint32_t)(a_row * ROW_B + a_c * 16);
            const size_t gb = (size_t)(bn + a_row) * K_DIM + kt + a_c * 8;
            cp16(sb + 2 * A_TILE + off,          g_Whi + gb);
            cp16(sb + 2 * A_TILE + B_TILE + off, g_Wlo + gb);
        }
    };

    float acc[2][4][4];
#pragma unroll
    for (int t = 0; t < 2; t++)
#pragma unroll
        for (int j = 0; j < 4; j++)
#pragma unroll
            for (int q = 0; q < 4; q++) acc[t][j][q] = 0.0f;

    const uint32_t a_lrow = (uint32_t)(wm * 32 + (lane & 15));
    const uint32_t a_lkof = (uint32_t)((lane >> 4) << 4);
    const int grp = lane >> 3;
    const uint32_t b_ln   = (uint32_t)(wn * 32 + ((grp >> 1) << 3) + (lane & 7));
    const uint32_t b_lkof = (uint32_t)((grp & 1) << 4);

    load_chunk(0, 0); CP_COMMIT();

    for (int c = 0; c < NC; c++) {
        const int s = c & 1;
        CP_WAIT0();            // chunk c resident (prefetched one iter ago)
        __syncthreads();       // everyone done with stage s^1's previous contents
        if (c + 1 < NC) { load_chunk(c + 1, s ^ 1); CP_COMMIT(); }

        const uint32_t sb = sbase + (uint32_t)s * STAGE_BYTES;
        const uint32_t sAhi = sb;
        const uint32_t sAlo = sb + A_TILE;
        const uint32_t sBhi = sb + 2 * A_TILE;
        const uint32_t sBlo = sb + 2 * A_TILE + B_TILE;

#pragma unroll
        for (int ks = 0; ks < 2; ks++) {
            uint32_t ah[2][4], al[2][4], bh[2][4], bl[2][4];
            const uint32_t akoff = (uint32_t)(ks * 32) + a_lkof;
            const uint32_t bkoff = (uint32_t)(ks * 32) + b_lkof;
#pragma unroll
            for (int t = 0; t < 2; t++) {
                const uint32_t aoff = (a_lrow + t * 16) * ROW_B + akoff;
                ldm_x4(ah[t], sAhi + aoff);
                ldm_x4(al[t], sAlo + aoff);
            }
#pragma unroll
            for (int p = 0; p < 2; p++) {
                const uint32_t boff = (b_ln + p * 16) * ROW_B + bkoff;
                ldm_x4(bh[p], sBhi + boff);
                ldm_x4(bl[p], sBlo + boff);
            }
#pragma unroll
            for (int t = 0; t < 2; t++) {
#pragma unroll
                for (int j = 0; j < 4; j++) {
                    const int p = j >> 1;
                    const int q = (j & 1) * 2;
                    mma16816(acc[t][j], ah[t], bh[p][q], bh[p][q + 1]);
                    mma16816(acc[t][j], ah[t], bl[p][q], bl[p][q + 1]);
                    mma16816(acc[t][j], al[t], bh[p][q], bh[p][q + 1]);
                }
            }
        }
    }

    // epilogue: bias + relu
    const int g  = lane >> 2;
    const int tg = lane & 3;
#pragma unroll
    for (int t = 0; t < 2; t++) {
#pragma unroll
        for (int j = 0; j < 4; j++) {
            const int col = wn * 32 + j * 8 + tg * 2;
            const float b0 = bias[bn + col];
            const float b1 = bias[bn + col + 1];
            const int row0 = bm + wm * 32 + t * 16 + g;
            float2 v0, v1;
            v0.x = fmaxf(acc[t][j][0] + b0, 0.0f);
            v0.y = fmaxf(acc[t][j][1] + b1, 0.0f);
            v1.x = fmaxf(acc[t][j][2] + b0, 0.0f);
            v1.y = fmaxf(acc[t][j][3] + b1, 0.0f);
            *reinterpret_cast<float2*>(out + (size_t)row0 * OUT_STRIDE + bn + col) = v0;
            *reinterpret_cast<float2*>(out + (size_t)(row0 + 8) * OUT_STRIDE + bn + col) = v1;
        }
    }
}

// ---------------- phrase mean: out[:, 1024:2048] ----------------
__global__ __launch_bounds__(256)
void phrase_mean_kernel(const float* __restrict__ phrases,
                        const int* __restrict__ lens,
                        float* __restrict__ out) {
    const int row = blockIdx.x;
    const int d4 = threadIdx.x;
    const float4* p = reinterpret_cast<const float4*>(phrases + (size_t)row * L_DIM * D_DIM) + d4;
    float4 s = make_float4(0.f, 0.f, 0.f, 0.f);
#pragma unroll
    for (int l = 0; l < L_DIM; l++) {
        float4 v = p[l * (D_DIM / 4)];
        s.x += v.x; s.y += v.y; s.z += v.z; s.w += v.w;
    }
    const float inv = 1.0f / (float)lens[row];
    s.x *= inv; s.y *= inv; s.z *= inv; s.w *= inv;
    reinterpret_cast<float4*>(out + (size_t)row * OUT_STRIDE + D_DIM)[d4] = s;
}

// ---------------- launch ----------------
extern "C" void kernel_launch(void* const* d_in, const int* in_sizes, int n_in,
                              void* d_out, int out_size) {
    const float* features = (const float*)d_in[0];
    const float* phrases  = (const float*)d_in[1];
    const float* W        = (const float*)d_in[2];
    const float* bias     = (const float*)d_in[3];
    const int*   lens     = (const int*)d_in[4];
    float* out = (float*)d_out;

    cudaFuncSetAttribute(gemm_mma_kernel, cudaFuncAttributeMaxDynamicSharedMemorySize, GEMM_SMEM);

    split_kernel<<<3072, 256>>>(features, W);
    phrase_mean_kernel<<<M_DIM, 256>>>(phrases, lens, out);

    dim3 grid(N_DIM / 64, M_DIM / 128);   // (16, 25) = 400 CTAs, one wave at 3 CTAs/SM
    gemm_mma_kernel<<<grid, 256, GEMM_SMEM>>>(bias, out);
}

// round 6
// speedup vs baseline: 1.5023x; 1.5023x over previous
#include <cuda_runtime.h>
#include <cuda_bf16.h>
#include <cstdint>

// Problem dims (fixed):
// features [3200, 4096] f32, phrases [3200, 15, 1024] f32,
// W [1024, 4096] f32, b [1024] f32, phrase_lengths [3200] i32
// out [3200, 2048] f32 : cols 0..1023 = relu(A@W^T + b), cols 1024..2047 = phrase mean
#define M_DIM 3200
#define N_DIM 1024
#define K_DIM 4096
#define OUT_STRIDE 2048
#define L_DIM 15
#define D_DIM 1024
#define KSPLIT 2
#define KHALF (K_DIM / KSPLIT)   // 2048

// ---------------- device-global buffers ----------------
__device__ __nv_bfloat16 g_Ahi[(size_t)M_DIM * K_DIM];
__device__ __nv_bfloat16 g_Alo[(size_t)M_DIM * K_DIM];
__device__ __nv_bfloat16 g_Whi[(size_t)N_DIM * K_DIM];
__device__ __nv_bfloat16 g_Wlo[(size_t)N_DIM * K_DIM];
__device__ float g_part[(size_t)KSPLIT * M_DIM * N_DIM];   // 26.2 MB partials

// ---------------- helpers ----------------
__device__ __forceinline__ uint32_t smem_to_u32(const void* p) {
    uint32_t a;
    asm("{ .reg .u64 t; cvta.to.shared.u64 t, %1; cvt.u32.u64 %0, t; }" : "=r"(a) : "l"(p));
    return a;
}
__device__ __forceinline__ void cp16(uint32_t dst, const void* src) {
    asm volatile("cp.async.cg.shared.global [%0], [%1], 16;" :: "r"(dst), "l"(src) : "memory");
}
#define CP_COMMIT() asm volatile("cp.async.commit_group;" ::: "memory")
#define CP_WAIT1()  asm volatile("cp.async.wait_group 1;" ::: "memory")
#define CP_WAIT0()  asm volatile("cp.async.wait_group 0;" ::: "memory")

__device__ __forceinline__ void ldm_x4(uint32_t* r, uint32_t addr) {
    asm volatile("ldmatrix.sync.aligned.m8n8.x4.shared.b16 {%0,%1,%2,%3}, [%4];"
                 : "=r"(r[0]), "=r"(r[1]), "=r"(r[2]), "=r"(r[3]) : "r"(addr));
}
__device__ __forceinline__ void mma16816(float* c, const uint32_t* a, uint32_t b0, uint32_t b1) {
    asm volatile(
        "mma.sync.aligned.m16n8k16.row.col.f32.bf16.bf16.f32 "
        "{%0,%1,%2,%3}, {%4,%5,%6,%7}, {%8,%9}, {%0,%1,%2,%3};"
        : "+f"(c[0]), "+f"(c[1]), "+f"(c[2]), "+f"(c[3])
        : "r"(a[0]), "r"(a[1]), "r"(a[2]), "r"(a[3]), "r"(b0), "r"(b1));
}

// ---------------- fused split prepass: fp32 -> bf16 hi + lo (A and W) ----------------
__device__ __forceinline__ void split4(const float4 v, __nv_bfloat162* hi2, __nv_bfloat162* lo2, int i) {
    __nv_bfloat16 hx = __float2bfloat16(v.x);
    __nv_bfloat16 hy = __float2bfloat16(v.y);
    __nv_bfloat16 hz = __float2bfloat16(v.z);
    __nv_bfloat16 hw = __float2bfloat16(v.w);
    hi2[2 * i]     = __halves2bfloat162(hx, hy);
    hi2[2 * i + 1] = __halves2bfloat162(hz, hw);
    lo2[2 * i]     = __floats2bfloat162_rn(v.x - __bfloat162float(hx), v.y - __bfloat162float(hy));
    lo2[2 * i + 1] = __floats2bfloat162_rn(v.z - __bfloat162float(hz), v.w - __bfloat162float(hw));
}
#define A_N4 (M_DIM * K_DIM / 4)
#define W_N4 (N_DIM * K_DIM / 4)
__global__ __launch_bounds__(256)
void split_kernel(const float* __restrict__ A, const float* __restrict__ W) {
    __nv_bfloat162* Ahi2 = reinterpret_cast<__nv_bfloat162*>(g_Ahi);
    __nv_bfloat162* Alo2 = reinterpret_cast<__nv_bfloat162*>(g_Alo);
    __nv_bfloat162* Whi2 = reinterpret_cast<__nv_bfloat162*>(g_Whi);
    __nv_bfloat162* Wlo2 = reinterpret_cast<__nv_bfloat162*>(g_Wlo);
    const float4* a4 = reinterpret_cast<const float4*>(A);
    const float4* w4 = reinterpret_cast<const float4*>(W);
    for (int i = blockIdx.x * blockDim.x + threadIdx.x; i < A_N4 + W_N4;
         i += gridDim.x * blockDim.x) {
        if (i < A_N4) split4(a4[i], Ahi2, Alo2, i);
        else          split4(w4[i - A_N4], Whi2, Wlo2, i - A_N4);
    }
}

// ---------------- mma.sync GEMM (split-K partials) ----------------
// BM=128, BN=64, BK=32 bf16. 8 warps, warp grid 4x2, warp tile 32x32.
// 3-stage cp.async pipeline, 80B padded rows, 2 CTAs/SM.
// Pass-major MMA order: all hh, then all hl, then all lh (dep distance 16).
#define BK 32
#define NC (KHALF / BK)          // 64
#define ROW_B 80
#define A_TILE (128 * ROW_B)
#define B_TILE (64 * ROW_B)
#define STAGE_BYTES (2 * A_TILE + 2 * B_TILE)   // 30720
#define NSTAGE 3
#define GEMM_SMEM (NSTAGE * STAGE_BYTES)        // 92160

__global__ __launch_bounds__(256, 2)
void gemm_mma_kernel() {
    extern __shared__ char smem[];
    const uint32_t sbase = smem_to_u32(smem);
    const int tid = threadIdx.x;
    const int wid = tid >> 5;
    const int lane = tid & 31;
    const int wm = wid >> 1;
    const int wn = wid & 1;
    const int bm = blockIdx.y * 128;
    const int bn = blockIdx.x * 64;
    const int kbase = blockIdx.z * KHALF;
    float* part = g_part + (size_t)blockIdx.z * M_DIM * N_DIM;

    const int a_row = tid >> 2;
    const int a_c   = tid & 3;

    auto load_chunk = [&](int chunk, int stage) {
        const int kt = kbase + chunk * BK;
        const uint32_t sb = sbase + (uint32_t)stage * STAGE_BYTES;
#pragma unroll
        for (int j = 0; j < 2; j++) {
            const int row = a_row + j * 64;
            const uint32_t off = (uint32_t)(row * ROW_B + a_c * 16);
            const size_t ga = (size_t)(bm + row) * K_DIM + kt + a_c * 8;
            cp16(sb + off,          g_Ahi + ga);
            cp16(sb + A_TILE + off, g_Alo + ga);
        }
        {
            const uint32_t off = (uint32_t)(a_row * ROW_B + a_c * 16);
            const size_t gb = (size_t)(bn + a_row) * K_DIM + kt + a_c * 8;
            cp16(sb + 2 * A_TILE + off,          g_Whi + gb);
            cp16(sb + 2 * A_TILE + B_TILE + off, g_Wlo + gb);
        }
    };

    float acc[2][4][4];
#pragma unroll
    for (int t = 0; t < 2; t++)
#pragma unroll
        for (int j = 0; j < 4; j++)
#pragma unroll
            for (int q = 0; q < 4; q++) acc[t][j][q] = 0.0f;

    const uint32_t a_lrow = (uint32_t)(wm * 32 + (lane & 15));
    const uint32_t a_lkof = (uint32_t)((lane >> 4) << 4);
    const int grp = lane >> 3;
    const uint32_t b_ln   = (uint32_t)(wn * 32 + ((grp >> 1) << 3) + (lane & 7));
    const uint32_t b_lkof = (uint32_t)((grp & 1) << 4);

    load_chunk(0, 0); CP_COMMIT();
    load_chunk(1, 1); CP_COMMIT();

    for (int c = 0; c < NC; c++) {
        if (c < NC - 1) { CP_WAIT1(); } else { CP_WAIT0(); }
        __syncthreads();

        const int nx = c + 2;
        if (nx < NC) { load_chunk(nx, nx % NSTAGE); CP_COMMIT(); }

        const uint32_t sb = sbase + (uint32_t)(c % NSTAGE) * STAGE_BYTES;
        const uint32_t sAhi = sb;
        const uint32_t sAlo = sb + A_TILE;
        const uint32_t sBhi = sb + 2 * A_TILE;
        const uint32_t sBlo = sb + 2 * A_TILE + B_TILE;

        // prefetch all fragments for both k-steps
        uint32_t ah[2][2][4], al[2][2][4], bh[2][2][4], bl[2][2][4];
#pragma unroll
        for (int ks = 0; ks < 2; ks++) {
            const uint32_t akoff = (uint32_t)(ks * 32) + a_lkof;
            const uint32_t bkoff = (uint32_t)(ks * 32) + b_lkof;
#pragma unroll
            for (int t = 0; t < 2; t++) {
                const uint32_t aoff = (a_lrow + t * 16) * ROW_B + akoff;
                ldm_x4(ah[ks][t], sAhi + aoff);
                ldm_x4(al[ks][t], sAlo + aoff);
            }
#pragma unroll
            for (int p = 0; p < 2; p++) {
                const uint32_t boff = (b_ln + p * 16) * ROW_B + bkoff;
                ldm_x4(bh[ks][p], sBhi + boff);
                ldm_x4(bl[ks][p], sBlo + boff);
            }
        }
        // pass-major: 16 independent MMAs per pass -> RAW distance 16
#pragma unroll
        for (int ks = 0; ks < 2; ks++)
#pragma unroll
            for (int t = 0; t < 2; t++)
#pragma unroll
                for (int j = 0; j < 4; j++) {
                    const int p = j >> 1;
                    const int q = (j & 1) * 2;
                    mma16816(acc[t][j], ah[ks][t], bh[ks][p][q], bh[ks][p][q + 1]);
                }
#pragma unroll
        for (int ks = 0; ks < 2; ks++)
#pragma unroll
            for (int t = 0; t < 2; t++)
#pragma unroll
                for (int j = 0; j < 4; j++) {
                    const int p = j >> 1;
                    const int q = (j & 1) * 2;
                    mma16816(acc[t][j], ah[ks][t], bl[ks][p][q], bl[ks][p][q + 1]);
                }
#pragma unroll
        for (int ks = 0; ks < 2; ks++)
#pragma unroll
            for (int t = 0; t < 2; t++)
#pragma unroll
                for (int j = 0; j < 4; j++) {
                    const int p = j >> 1;
                    const int q = (j & 1) * 2;
                    mma16816(acc[t][j], al[ks][t], bh[ks][p][q], bh[ks][p][q + 1]);
                }
    }

    // epilogue: raw fp32 partials, stride N_DIM
    const int g  = lane >> 2;
    const int tg = lane & 3;
#pragma unroll
    for (int t = 0; t < 2; t++) {
#pragma unroll
        for (int j = 0; j < 4; j++) {
            const int col = bn + wn * 32 + j * 8 + tg * 2;
            const int row0 = bm + wm * 32 + t * 16 + g;
            float2 v0, v1;
            v0.x = acc[t][j][0]; v0.y = acc[t][j][1];
            v1.x = acc[t][j][2]; v1.y = acc[t][j][3];
            *reinterpret_cast<float2*>(part + (size_t)row0 * N_DIM + col) = v0;
            *reinterpret_cast<float2*>(part + (size_t)(row0 + 8) * N_DIM + col) = v1;
        }
    }
}

// ---------------- reduce: out[:,0:1024] = relu(p0 + p1 + bias) ----------------
__global__ __launch_bounds__(256)
void reduce_kernel(const float* __restrict__ bias, float* __restrict__ out) {
    const int row = blockIdx.x;
    const int c4 = threadIdx.x;          // float4 index over 1024 cols
    const size_t off = (size_t)row * (N_DIM / 4) + c4;
    const float4 p0 = reinterpret_cast<const float4*>(g_part)[off];
    const float4 p1 = reinterpret_cast<const float4*>(g_part + (size_t)M_DIM * N_DIM)[off];
    const float4 bv = reinterpret_cast<const float4*>(bias)[c4];
    float4 v;
    v.x = fmaxf(p0.x + p1.x + bv.x, 0.0f);
    v.y = fmaxf(p0.y + p1.y + bv.y, 0.0f);
    v.z = fmaxf(p0.z + p1.z + bv.z, 0.0f);
    v.w = fmaxf(p0.w + p1.w + bv.w, 0.0f);
    reinterpret_cast<float4*>(out + (size_t)row * OUT_STRIDE)[c4] = v;
}

// ---------------- phrase mean: out[:, 1024:2048] ----------------
__global__ __launch_bounds__(256)
void phrase_mean_kernel(const float* __restrict__ phrases,
                        const int* __restrict__ lens,
                        float* __restrict__ out) {
    const int row = blockIdx.x;
    const int d4 = threadIdx.x;
    const float4* p = reinterpret_cast<const float4*>(phrases + (size_t)row * L_DIM * D_DIM) + d4;
    float4 s = make_float4(0.f, 0.f, 0.f, 0.f);
#pragma unroll
    for (int l = 0; l < L_DIM; l++) {
        float4 v = p[l * (D_DIM / 4)];
        s.x += v.x; s.y += v.y; s.z += v.z; s.w += v.w;
    }
    const float inv = 1.0f / (float)lens[row];
    s.x *= inv; s.y *= inv; s.z *= inv; s.w *= inv;
    reinterpret_cast<float4*>(out + (size_t)row * OUT_STRIDE + D_DIM)[d4] = s;
}

// ---------------- launch ----------------
extern "C" void kernel_launch(void* const* d_in, const int* in_sizes, int n_in,
                              void* d_out, int out_size) {
    const float* features = (const float*)d_in[0];
    const float* phrases  = (const float*)d_in[1];
    const float* W        = (const float*)d_in[2];
    const float* bias     = (const float*)d_in[3];
    const int*   lens     = (const int*)d_in[4];
    float* out = (float*)d_out;

    cudaFuncSetAttribute(gemm_mma_kernel, cudaFuncAttributeMaxDynamicSharedMemorySize, GEMM_SMEM);

    split_kernel<<<3072, 256>>>(features, W);
    phrase_mean_kernel<<<M_DIM, 256>>>(phrases, lens, out);

    dim3 grid(N_DIM / 64, M_DIM / 128, KSPLIT);   // (16, 25, 2) = 800 CTAs
    gemm_mma_kernel<<<grid, 256, GEMM_SMEM>>>();

    reduce_kernel<<<M_DIM, 256>>>(bias, out);
}